// round 2
// baseline (speedup 1.0000x reference)
#include <cuda_runtime.h>

// Problem constants (fixed by the dataset)
#define BB    2
#define NEV   262144          // 2^18 events per batch
#define DBASE 10
#define HH    256
#define WW    256
#define RR    11              // base + 1 references
#define HWSZ  (HH * WW)       // 65536
#define CELLS (BB * 2 * RR * HWSZ)  // 2,883,584 float2 cells (~23 MB)

// Scratch accumulator: .x = iwe (event count weight), .y = iwt (weight * timestamp)
__device__ float2 g_grid[CELLS];

// ---------------------------------------------------------------------------
// Kernel 1: zero the accumulator grid (float4 stores)
// ---------------------------------------------------------------------------
__global__ void cm_zero_kernel() {
    float4* g = reinterpret_cast<float4*>(g_grid);
    const int n4 = CELLS / 2;  // 2 floats per cell -> /4 floats per float4 => CELLS/2
    int i = blockIdx.x * blockDim.x + threadIdx.x;
    int stride = gridDim.x * blockDim.x;
    float4 z = make_float4(0.f, 0.f, 0.f, 0.f);
    for (; i < n4; i += stride) g[i] = z;
}

// ---------------------------------------------------------------------------
// Kernel 2: per-event flow sample + bilinear scatter into all R references
// ---------------------------------------------------------------------------
__global__ void __launch_bounds__(256)
cm_scatter_kernel(const float* __restrict__ events,
                  const float2* __restrict__ flow) {
    int e = blockIdx.x * blockDim.x + threadIdx.x;
    if (e >= BB * NEV) return;
    int b = e >> 18;  // e / NEV

    const float* ev = events + (size_t)e * 5;
    float x  = ev[0];
    float y  = ev[1];
    float t  = ev[2];
    float ts = ev[3];
    float p  = ev[4];

    int pi = (int)p;
    pi = min(max(pi, 0), 1);
    int zi = (int)floorf(t);
    zi = min(max(zi, 0), DBASE - 1);

    // --- bilinear flow sample at (x, y), border-clamped like reference ---
    int sx0 = (int)floorf(x); sx0 = min(max(sx0, 0), WW - 2);
    int sy0 = (int)floorf(y); sy0 = min(max(sy0, 0), HH - 2);
    float fx = fminf(fmaxf(x - (float)sx0, 0.f), 1.f);
    float fy = fminf(fmaxf(y - (float)sy0, 0.f), 1.f);

    const float2* fm = flow + (((size_t)(b * DBASE + zi) * HH + sy0) * WW + sx0);
    float2 f00 = fm[0];
    float2 f01 = fm[1];
    float2 f10 = fm[WW];
    float2 f11 = fm[WW + 1];

    float w00s = (1.f - fx) * (1.f - fy);
    float w01s = fx * (1.f - fy);
    float w10s = (1.f - fx) * fy;
    float w11s = fx * fy;
    float fu = w00s * f00.x + w01s * f01.x + w10s * f10.x + w11s * f11.x;
    float fv = w00s * f00.y + w01s * f01.y + w10s * f10.y + w11s * f11.y;

    float2* chan = g_grid + (size_t)((b * 2 + pi) * RR) * HWSZ;

    #pragma unroll
    for (int r = 0; r < RR; r++) {
        float dt = (float)r - t;
        float wx = fmaf(dt, fu, x);
        float wy = fmaf(dt, fv, y);
        float flx = floorf(wx);
        float fly = floorf(wy);
        int x0 = (int)flx;
        int y0 = (int)fly;
        float ax = wx - flx;
        float ay = wy - fly;

        float c00 = (1.f - ax) * (1.f - ay);
        float c01 = ax * (1.f - ay);
        float c10 = (1.f - ax) * ay;
        float c11 = ax * ay;

        bool vx0 = (unsigned)x0 < (unsigned)WW;
        bool vx1 = (unsigned)(x0 + 1) < (unsigned)WW;
        bool vy0 = (unsigned)y0 < (unsigned)HH;
        bool vy1 = (unsigned)(y0 + 1) < (unsigned)HH;

        float2* cell = chan + r * HWSZ + y0 * WW + x0;
        if (vx0 && vy0) atomicAdd(cell,          make_float2(c00, c00 * ts));
        if (vx1 && vy0) atomicAdd(cell + 1,      make_float2(c01, c01 * ts));
        if (vx0 && vy1) atomicAdd(cell + WW,     make_float2(c10, c10 * ts));
        if (vx1 && vy1) atomicAdd(cell + WW + 1, make_float2(c11, c11 * ts));
    }
}

// ---------------------------------------------------------------------------
// Kernel 3: per-(b, r) contrast reduction -> out[b*R + r] = loss / inside
// ---------------------------------------------------------------------------
__global__ void __launch_bounds__(256)
cm_reduce_kernel(float* __restrict__ out) {
    const int br = blockIdx.x;      // 0 .. B*R-1
    const int b = br / RR;
    const int r = br % RR;
    const int tid = threadIdx.x;

    const float2* neg = g_grid + (size_t)((b * 2 + 0) * RR + r) * HWSZ;
    const float2* pos = g_grid + (size_t)((b * 2 + 1) * RR + r) * HWSZ;

    float loss = 0.f;
    float inside = 0.f;
    for (int i = tid; i < HWSZ; i += blockDim.x) {
        float2 cn = neg[i];
        float2 cp = pos[i];
        float an = cn.y / (cn.x + 1e-9f);
        float ap = cp.y / (cp.x + 1e-9f);
        loss = fmaf(an, an, loss);
        loss = fmaf(ap, ap, loss);
        if (cn.x + cp.x > 0.f) inside += 1.f;
    }

    __shared__ float sl[256];
    __shared__ float si[256];
    sl[tid] = loss;
    si[tid] = inside;
    __syncthreads();
    for (int s = 128; s > 0; s >>= 1) {
        if (tid < s) {
            sl[tid] += sl[tid + s];
            si[tid] += si[tid + s];
        }
        __syncthreads();
    }
    if (tid == 0) out[br] = sl[0] / (si[0] + 1e-9f);
}

// ---------------------------------------------------------------------------
extern "C" void kernel_launch(void* const* d_in, const int* in_sizes, int n_in,
                              void* d_out, int out_size) {
    const float*  events = (const float*)d_in[0];
    const float2* flow   = (const float2*)d_in[1];
    float* out = (float*)d_out;

    // 1) zero the 23 MB accumulator grid
    cm_zero_kernel<<<2048, 256>>>();

    // 2) scatter all B*N events into all R references
    cm_scatter_kernel<<<(BB * NEV + 255) / 256, 256>>>(events, flow);

    // 3) reduce each (b, r) slice to a single loss value
    cm_reduce_kernel<<<BB * RR, 256>>>(out);
}

// round 3
// speedup vs baseline: 3.6212x; 3.6212x over previous
#include <cuda_runtime.h>

// Problem constants (fixed by the dataset)
#define BB    2
#define NEV   262144          // 2^18 events per batch
#define DBASE 10
#define HH    256
#define WW    256
#define RR    11              // base + 1 references
#define HWSZ  (HH * WW)       // 65536
#define CELLS (BB * 2 * RR * HWSZ)  // 2,883,584 float2 cells (~23 MB each grid)
#define PAD   1024            // guard cells each side (window can poke +-1 cell / cross channel w/ zero weight)

// Two accumulator grids. Each cell: .x = iwe weight, .y = iwe*timestamp.
// A grid:  16B-aligned float4 windows for even x0.
// B grid:  logically shifted by one float2 so odd-x0 windows are 16B-aligned.
__device__ __align__(16) float2 g_A[CELLS + 2 * PAD];          // cell j at g_A + PAD + j
__device__ __align__(16) float2 g_Braw[CELLS + 2 * PAD + 2];   // cell j at g_Braw + 1 + PAD + j
__device__ float2 g_partial[BB * RR];                          // {loss, inside} partials

// ---------------------------------------------------------------------------
// Kernel 1: zero both grids + partials
// ---------------------------------------------------------------------------
__global__ void cm_zero_kernel() {
    const int nA = (CELLS + 2 * PAD) / 2;        // float4 count in A
    const int nB = (CELLS + 2 * PAD + 2) / 2;    // float4 count in B
    float4* a = reinterpret_cast<float4*>(g_A);
    float4* bq = reinterpret_cast<float4*>(g_Braw);
    float4 z = make_float4(0.f, 0.f, 0.f, 0.f);
    int i = blockIdx.x * blockDim.x + threadIdx.x;
    int stride = gridDim.x * blockDim.x;
    for (int j = i; j < nA; j += stride) a[j] = z;
    for (int j = i; j < nB; j += stride) bq[j] = z;
    if (i < BB * RR) g_partial[i] = make_float2(0.f, 0.f);
}

// ---------------------------------------------------------------------------
// Kernel 2: per-event flow sample + bilinear scatter (2x float4 RED per ref)
// ---------------------------------------------------------------------------
__global__ void __launch_bounds__(256)
cm_scatter_kernel(const float* __restrict__ events,
                  const float2* __restrict__ flow) {
    int e = blockIdx.x * blockDim.x + threadIdx.x;
    if (e >= BB * NEV) return;
    int b = e >> 18;  // e / NEV

    const float* ev = events + (size_t)e * 5;
    float x  = ev[0];
    float y  = ev[1];
    float t  = ev[2];
    float ts = ev[3];
    float p  = ev[4];

    int pi = min(max((int)p, 0), 1);
    int zi = min(max((int)floorf(t), 0), DBASE - 1);

    // --- bilinear flow sample at (x, y), border-clamped like reference ---
    int sx0 = min(max((int)floorf(x), 0), WW - 2);
    int sy0 = min(max((int)floorf(y), 0), HH - 2);
    float fx = fminf(fmaxf(x - (float)sx0, 0.f), 1.f);
    float fy = fminf(fmaxf(y - (float)sy0, 0.f), 1.f);

    const float2* fm = flow + (((size_t)(b * DBASE + zi) * HH + sy0) * WW + sx0);
    float2 f00 = fm[0];
    float2 f01 = fm[1];
    float2 f10 = fm[WW];
    float2 f11 = fm[WW + 1];

    float w00s = (1.f - fx) * (1.f - fy);
    float w01s = fx * (1.f - fy);
    float w10s = (1.f - fx) * fy;
    float w11s = fx * fy;
    float fu = w00s * f00.x + w01s * f01.x + w10s * f10.x + w11s * f11.x;
    float fv = w00s * f00.y + w01s * f01.y + w10s * f10.y + w11s * f11.y;

    const int chan0 = ((b * 2 + pi) * RR) * HWSZ;
    float2* baseA = g_A + PAD + chan0;
    float2* baseB = g_Braw + 1 + PAD + chan0;

    #pragma unroll
    for (int r = 0; r < RR; r++) {
        float dt = (float)r - t;
        float wx = fmaf(dt, fu, x);
        float wy = fmaf(dt, fv, y);
        float flx = floorf(wx);
        float fly = floorf(wy);
        int x0 = (int)flx;
        int y0 = (int)fly;

        bool vx0 = (unsigned)x0 < (unsigned)WW;
        bool vx1 = (unsigned)(x0 + 1) < (unsigned)WW;
        if (!(vx0 | vx1)) continue;               // whole column pair off-screen

        float ax = wx - flx;
        float ay = wy - fly;
        float wl = vx0 ? (1.f - ax) : 0.f;        // left column weight
        float wr = vx1 ? ax : 0.f;                // right column weight
        float wlt = wl * ts;
        float wrt = wr * ts;

        // pick grid by x0 parity so the 16B window is aligned
        float2* gb = (x0 & 1) ? baseB : baseA;
        int off = r * HWSZ + y0 * WW + x0;

        if ((unsigned)y0 < (unsigned)HH) {
            float s0 = 1.f - ay;
            atomicAdd(reinterpret_cast<float4*>(gb + off),
                      make_float4(wl * s0, wlt * s0, wr * s0, wrt * s0));
        }
        if ((unsigned)(y0 + 1) < (unsigned)HH) {
            atomicAdd(reinterpret_cast<float4*>(gb + off + WW),
                      make_float4(wl * ay, wlt * ay, wr * ay, wrt * ay));
        }
    }
}

// ---------------------------------------------------------------------------
// Kernel 3: partial contrast reduction, SPLIT blocks per (b, r)
// ---------------------------------------------------------------------------
#define SPLIT 8
__global__ void __launch_bounds__(256)
cm_reduce_kernel() {
    const int blk = blockIdx.x;
    const int br = blk / SPLIT;                 // 0 .. B*R-1
    const int part = blk % SPLIT;
    const int b = br / RR;
    const int r = br % RR;
    const int tid = threadIdx.x;

    const int chanN = ((b * 2 + 0) * RR + r) * HWSZ;
    const int chanP = ((b * 2 + 1) * RR + r) * HWSZ;
    const float2* An = g_A + PAD + chanN;
    const float2* Bn = g_Braw + 1 + PAD + chanN;
    const float2* Ap = g_A + PAD + chanP;
    const float2* Bp = g_Braw + 1 + PAD + chanP;

    const int per = HWSZ / SPLIT;
    const int lo = part * per;
    const int hi = lo + per;

    float loss = 0.f;
    float inside = 0.f;
    for (int i = lo + tid; i < hi; i += blockDim.x) {
        float2 an2 = An[i], bn2 = Bn[i];
        float2 ap2 = Ap[i], bp2 = Bp[i];
        float nwe = an2.x + bn2.x;
        float nwt = an2.y + bn2.y;
        float pwe = ap2.x + bp2.x;
        float pwt = ap2.y + bp2.y;
        float an = nwt / (nwe + 1e-9f);
        float ap = pwt / (pwe + 1e-9f);
        loss = fmaf(an, an, loss);
        loss = fmaf(ap, ap, loss);
        if (nwe + pwe > 0.f) inside += 1.f;
    }

    __shared__ float sl[256];
    __shared__ float si[256];
    sl[tid] = loss;
    si[tid] = inside;
    __syncthreads();
    for (int s = 128; s > 0; s >>= 1) {
        if (tid < s) {
            sl[tid] += sl[tid + s];
            si[tid] += si[tid + s];
        }
        __syncthreads();
    }
    if (tid == 0) atomicAdd(&g_partial[br], make_float2(sl[0], si[0]));
}

// ---------------------------------------------------------------------------
// Kernel 4: finalize 22 outputs
// ---------------------------------------------------------------------------
__global__ void cm_final_kernel(float* __restrict__ out) {
    int i = threadIdx.x;
    if (i < BB * RR) {
        float2 v = g_partial[i];
        out[i] = v.x / (v.y + 1e-9f);
    }
}

// ---------------------------------------------------------------------------
extern "C" void kernel_launch(void* const* d_in, const int* in_sizes, int n_in,
                              void* d_out, int out_size) {
    const float*  events = (const float*)d_in[0];
    const float2* flow   = (const float2*)d_in[1];
    float* out = (float*)d_out;

    cm_zero_kernel<<<4096, 256>>>();
    cm_scatter_kernel<<<(BB * NEV + 255) / 256, 256>>>(events, flow);
    cm_reduce_kernel<<<BB * RR * SPLIT, 256>>>();
    cm_final_kernel<<<1, 32>>>(out);
}

// round 5
// speedup vs baseline: 4.0338x; 1.1139x over previous
#include <cuda_runtime.h>

// Problem constants (fixed by the dataset)
#define BB    2
#define NEV   262144          // 2^18 events per batch
#define DBASE 10
#define HH    256
#define WW    256
#define RR    11              // base + 1 references
#define HWSZ  (HH * WW)       // 65536
#define CELLS (BB * 2 * RR * HWSZ)  // 2,883,584 float2 cells (~23 MB per grid)
#define PAD   1024            // guard cells (zero-weight strays)

// Combined scratch buffer, cleared with ONE memset:
//   A grid  : cells at  [OFF_A + PAD + j]        (even-x0 16B-aligned windows)
//   B grid  : cells at  [OFF_B + 1 + PAD + j]    (odd-x0 16B-aligned windows)
//   partials: BB*RR float2 {loss, inside}
//   counter : one int (block completion count)
#define OFF_A 0
#define OFF_B (CELLS + 2 * PAD)
#define OFF_P (OFF_B + CELLS + 2 * PAD + 2)
#define OFF_C (OFF_P + BB * RR)
#define TOT2  (OFF_C + 1)

__device__ __align__(16) float2 g_buf[TOT2];

#define SPLIT 16
#define NRBLK (BB * RR * SPLIT)

// ---------------------------------------------------------------------------
// Kernel 1: per-event flow sample + bilinear scatter (2x float4 RED per ref)
// ---------------------------------------------------------------------------
__global__ void __launch_bounds__(256)
cm_scatter_kernel(const float* __restrict__ events,
                  const float2* __restrict__ flow) {
    int e = blockIdx.x * blockDim.x + threadIdx.x;
    if (e >= BB * NEV) return;
    int b = e >> 18;  // e / NEV

    const float* ev = events + (size_t)e * 5;
    float x  = ev[0];
    float y  = ev[1];
    float t  = ev[2];
    float ts = ev[3];
    float p  = ev[4];

    int pi = min(max((int)p, 0), 1);
    int zi = min(max((int)floorf(t), 0), DBASE - 1);

    // --- bilinear flow sample at (x, y), border-clamped like reference ---
    int sx0 = min(max((int)floorf(x), 0), WW - 2);
    int sy0 = min(max((int)floorf(y), 0), HH - 2);
    float fx = fminf(fmaxf(x - (float)sx0, 0.f), 1.f);
    float fy = fminf(fmaxf(y - (float)sy0, 0.f), 1.f);

    const float2* fm = flow + (((size_t)(b * DBASE + zi) * HH + sy0) * WW + sx0);
    float2 f00 = fm[0];
    float2 f01 = fm[1];
    float2 f10 = fm[WW];
    float2 f11 = fm[WW + 1];

    float w00s = (1.f - fx) * (1.f - fy);
    float w01s = fx * (1.f - fy);
    float w10s = (1.f - fx) * fy;
    float w11s = fx * fy;
    float fu = w00s * f00.x + w01s * f01.x + w10s * f10.x + w11s * f11.x;
    float fv = w00s * f00.y + w01s * f01.y + w10s * f10.y + w11s * f11.y;

    const int chan0 = ((b * 2 + pi) * RR) * HWSZ;
    float2* baseA = g_buf + OFF_A + PAD + chan0;
    float2* baseB = g_buf + OFF_B + 1 + PAD + chan0;

    #pragma unroll
    for (int r = 0; r < RR; r++) {
        float dt = (float)r - t;
        float wx = fmaf(dt, fu, x);
        float wy = fmaf(dt, fv, y);
        float flx = floorf(wx);
        float fly = floorf(wy);
        int x0 = (int)flx;
        int y0 = (int)fly;

        bool vx0 = (unsigned)x0 < (unsigned)WW;
        bool vx1 = (unsigned)(x0 + 1) < (unsigned)WW;
        if (!(vx0 | vx1)) continue;               // whole column pair off-screen

        float ax = wx - flx;
        float ay = wy - fly;
        float wl = vx0 ? (1.f - ax) : 0.f;        // left column weight
        float wr = vx1 ? ax : 0.f;                // right column weight
        float wlt = wl * ts;
        float wrt = wr * ts;

        // pick grid by x0 parity so the 16B window is aligned
        float2* gb = (x0 & 1) ? baseB : baseA;
        int off = r * HWSZ + y0 * WW + x0;

        if ((unsigned)y0 < (unsigned)HH) {
            float s0 = 1.f - ay;
            atomicAdd(reinterpret_cast<float4*>(gb + off),
                      make_float4(wl * s0, wlt * s0, wr * s0, wrt * s0));
        }
        if ((unsigned)(y0 + 1) < (unsigned)HH) {
            atomicAdd(reinterpret_cast<float4*>(gb + off + WW),
                      make_float4(wl * ay, wlt * ay, wr * ay, wrt * ay));
        }
    }
}

// ---------------------------------------------------------------------------
// Kernel 2: partial contrast reduction + fused finalize (last block writes out)
// ---------------------------------------------------------------------------
__global__ void __launch_bounds__(256)
cm_reduce_kernel(float* __restrict__ out) {
    const int blk = blockIdx.x;
    const int br = blk / SPLIT;                 // 0 .. B*R-1
    const int part = blk % SPLIT;
    const int b = br / RR;
    const int r = br % RR;
    const int tid = threadIdx.x;

    const int chanN = ((b * 2 + 0) * RR + r) * HWSZ;
    const int chanP = ((b * 2 + 1) * RR + r) * HWSZ;
    const float2* An = g_buf + OFF_A + PAD + chanN;
    const float2* Bn = g_buf + OFF_B + 1 + PAD + chanN;
    const float2* Ap = g_buf + OFF_A + PAD + chanP;
    const float2* Bp = g_buf + OFF_B + 1 + PAD + chanP;

    const int per = HWSZ / SPLIT;               // 4096 cells
    const int lo = part * per;

    float loss = 0.f;
    float inside = 0.f;
    // 2 cells per thread-iteration; A read as float4 (16B-aligned at even i)
    for (int i = lo + tid * 2; i < lo + per; i += blockDim.x * 2) {
        float4 a4n = *reinterpret_cast<const float4*>(An + i);
        float4 a4p = *reinterpret_cast<const float4*>(Ap + i);
        float2 bn0 = Bn[i], bn1 = Bn[i + 1];
        float2 bp0 = Bp[i], bp1 = Bp[i + 1];

        float nwe0 = a4n.x + bn0.x, nwt0 = a4n.y + bn0.y;
        float nwe1 = a4n.z + bn1.x, nwt1 = a4n.w + bn1.y;
        float pwe0 = a4p.x + bp0.x, pwt0 = a4p.y + bp0.y;
        float pwe1 = a4p.z + bp1.x, pwt1 = a4p.w + bp1.y;

        float an0 = nwt0 / (nwe0 + 1e-9f);
        float an1 = nwt1 / (nwe1 + 1e-9f);
        float ap0 = pwt0 / (pwe0 + 1e-9f);
        float ap1 = pwt1 / (pwe1 + 1e-9f);
        loss = fmaf(an0, an0, loss);
        loss = fmaf(an1, an1, loss);
        loss = fmaf(ap0, ap0, loss);
        loss = fmaf(ap1, ap1, loss);
        if (nwe0 + pwe0 > 0.f) inside += 1.f;
        if (nwe1 + pwe1 > 0.f) inside += 1.f;
    }

    __shared__ float sl[256];
    __shared__ float si[256];
    sl[tid] = loss;
    si[tid] = inside;
    __syncthreads();
    for (int s = 128; s > 0; s >>= 1) {
        if (tid < s) {
            sl[tid] += sl[tid + s];
            si[tid] += si[tid + s];
        }
        __syncthreads();
    }

    __shared__ int s_last;
    if (tid == 0) {
        float2* partial = g_buf + OFF_P;
        atomicAdd(&partial[br].x, sl[0]);
        atomicAdd(&partial[br].y, si[0]);
        __threadfence();
        int* cnt = reinterpret_cast<int*>(g_buf + OFF_C);
        int done = atomicAdd(cnt, 1);
        s_last = (done == NRBLK - 1) ? 1 : 0;
    }
    __syncthreads();

    if (s_last && tid < BB * RR) {
        float* partial = reinterpret_cast<float*>(g_buf + OFF_P);
        // atomic reads ensure we see other blocks' L2-resident adds
        float lv = atomicAdd(&partial[tid * 2 + 0], 0.f);
        float iv = atomicAdd(&partial[tid * 2 + 1], 0.f);
        out[tid] = lv / (iv + 1e-9f);
    }
}

// ---------------------------------------------------------------------------
extern "C" void kernel_launch(void* const* d_in, const int* in_sizes, int n_in,
                              void* d_out, int out_size) {
    const float*  events = (const float*)d_in[0];
    const float2* flow   = (const float2*)d_in[1];
    float* out = (float*)d_out;

    void* bufp = nullptr;
    cudaGetSymbolAddress(&bufp, g_buf);

    // 1) clear grids + partials + counter in one memset node
    cudaMemsetAsync(bufp, 0, sizeof(float2) * TOT2);

    // 2) scatter all B*N events into all R references
    cm_scatter_kernel<<<(BB * NEV + 255) / 256, 256>>>(events, flow);

    // 3) reduce each (b, r) slice; last block finalizes the 22 outputs
    cm_reduce_kernel<<<NRBLK, 256>>>(out);
}